// round 15
// baseline (speedup 1.0000x reference)
#include <cuda_runtime.h>
#include <math.h>
#include <cstdint>

#define D_MODEL   1024
#define NUM_HEADS 16
#define HEAD_DIM  64
#define BATCH     4
#define SEQ       2048
#define ROWS      (BATCH * SEQ)   // 8192

// Scratch (allocation-free rule: __device__ globals)
__device__ float g_Q[ROWS * D_MODEL];
__device__ float g_K[ROWS * D_MODEL];
__device__ float g_V[ROWS * D_MODEL];
__device__ float g_O[ROWS * D_MODEL];
__device__ float g_WT[4 * D_MODEL * D_MODEL];   // transposed+rounded weights

// ===========================================================================
// Helpers (arch-agnostic PTX only: cp.async + ldmatrix + mma.sync tf32)
// ===========================================================================
__device__ __forceinline__ uint32_t smem_u32(const void* p) {
    uint32_t a;
    asm("{ .reg .u64 t; cvta.to.shared.u64 t, %1; cvt.u32.u64 %0, t; }"
        : "=r"(a) : "l"(p));
    return a;
}
__device__ __forceinline__ void cp_async16(uint32_t dst, const void* src) {
    asm volatile("cp.async.cg.shared.global [%0], [%1], 16;"
                 :: "r"(dst), "l"(src) : "memory");
}
__device__ __forceinline__ void cp_commit() {
    asm volatile("cp.async.commit_group;" ::: "memory");
}
template <int N>
__device__ __forceinline__ void cp_wait() {
    asm volatile("cp.async.wait_group %0;" :: "n"(N) : "memory");
}
__device__ __forceinline__ float f2tf_f(float x) {
    uint32_t r;
    asm("cvt.rna.tf32.f32 %0, %1;" : "=r"(r) : "f"(x));
    return __uint_as_float(r);
}
__device__ __forceinline__ uint32_t f2tf_u(uint32_t x) {
    uint32_t r;
    asm("cvt.rna.tf32.f32 %0, %1;" : "=r"(r) : "r"(x));
    return r;
}
__device__ __forceinline__ void ldsm4(uint32_t* r, uint32_t addr) {
    asm volatile("ldmatrix.sync.aligned.m8n8.x4.shared.b16 {%0,%1,%2,%3}, [%4];"
                 : "=r"(r[0]), "=r"(r[1]), "=r"(r[2]), "=r"(r[3]) : "r"(addr));
}
__device__ __forceinline__ void mma_tf32(float* c, const uint32_t* a,
                                         const uint32_t* b) {
    asm volatile(
        "mma.sync.aligned.m16n8k8.row.col.f32.tf32.tf32.f32 "
        "{%0,%1,%2,%3}, {%4,%5,%6,%7}, {%8,%9}, {%0,%1,%2,%3};"
        : "+f"(c[0]), "+f"(c[1]), "+f"(c[2]), "+f"(c[3])
        : "r"(a[0]), "r"(a[1]), "r"(a[2]), "r"(a[3]), "r"(b[0]), "r"(b[1]));
}

// ===========================================================================
// Fused weight transpose + tf32 round: WT_z[n][k] = round(W_z[k][n]), z=0..3
// ===========================================================================
__global__ void __launch_bounds__(256) transpose_kernel(
    const float* __restrict__ w0, const float* __restrict__ w1,
    const float* __restrict__ w2, const float* __restrict__ w3,
    float* __restrict__ outbase)
{
    __shared__ float t[32][33];
    const int z = blockIdx.z;
    const float* in = (z == 0) ? w0 : (z == 1) ? w1 : (z == 2) ? w2 : w3;
    float* out = outbase + (size_t)z * D_MODEL * D_MODEL;
    const int bx = blockIdx.x * 32, by = blockIdx.y * 32;
#pragma unroll
    for (int i = threadIdx.y; i < 32; i += 8)
        t[i][threadIdx.x] = f2tf_f(in[(size_t)(by + i) * D_MODEL + bx + threadIdx.x]);
    __syncthreads();
#pragma unroll
    for (int i = threadIdx.y; i < 32; i += 8)
        out[(size_t)(bx + i) * D_MODEL + by + threadIdx.x] = t[threadIdx.x][i];
}

// ===========================================================================
// TF32 mma.sync GEMM core. CTA 128x128, BK=16, 8 warps, warp 64x32.
// 3-stage cp.async ring, one __syncthreads per k-iter, 3 CTAs/SM target.
// Register diet: single ldsm base addr per operand, bf loaded pair-at-a-time.
// ===========================================================================
#define BK      16
#define SSTR    20
#define NKIT    (D_MODEL / BK)        // 64
#define BUFF    (128 * SSTR)          // floats per buffer (2560)
#define BUFB    (BUFF * 4)            // bytes per buffer (10240)
#define ROWSKIP (16 * SSTR * 4)       // 16 rows of smem = 1280 bytes
static constexpr int GEMM_SMEM = 6 * BUFB;   // 3 stages x (A+B) = 61440 B

template <int DO_CVT>
__device__ __forceinline__ void gemm_body(
    const float* __restrict__ X, const float* __restrict__ WT,
    const float* __restrict__ bias, const int* __restrict__ pos,
    float* __restrict__ out, bool do_rope, bool do_round, float oscale,
    float* __restrict__ As, float* __restrict__ Bs,
    int row0, int col0)
{
    const int tid  = threadIdx.x;
    const int wid  = tid >> 5, lane = tid & 31;
    const int g    = lane >> 2;
    const int t    = lane & 3;
    const int warpM = (wid >> 2) * 64;
    const int warpN = (wid & 3) * 32;

    // single base address per operand; per-tile offsets are immediates
    const uint32_t aBase = smem_u32(
        &As[(warpM + (lane & 15)) * SSTR + (lane >> 4) * 4]);
    const uint32_t bBase = smem_u32(
        &Bs[(warpN + (lane >> 4) * 8 + (lane & 7)) * SSTR + ((lane >> 3) & 1) * 4]);

    float c[4][4][4];
#pragma unroll
    for (int i = 0; i < 4; i++)
#pragma unroll
        for (int j = 0; j < 4; j++)
#pragma unroll
            for (int q = 0; q < 4; q++) c[i][j][q] = 0.f;

    auto stage = [&](int buf, int it) {
        const float* aSrc = X  + (size_t)row0 * D_MODEL + it * BK;
        const float* bSrc = WT + (size_t)col0 * D_MODEL + it * BK;
#pragma unroll
        for (int rep = 0; rep < 2; rep++) {
            int idx = rep * 256 + tid;          // 0..511
            int r = idx >> 2, c4 = (idx & 3) * 4;
            cp_async16(smem_u32(&As[buf * BUFF + r * SSTR + c4]),
                       aSrc + (size_t)r * D_MODEL + c4);
            cp_async16(smem_u32(&Bs[buf * BUFF + r * SSTR + c4]),
                       bSrc + (size_t)r * D_MODEL + c4);
        }
        cp_commit();
    };

    stage(0, 0);
    stage(1, 1);

#pragma unroll 1
    for (int it = 0; it < NKIT; it++) {
        if (it + 1 < NKIT) cp_wait<1>(); else cp_wait<0>();
        __syncthreads();
        if (it + 2 < NKIT) stage((it + 2) % 3, it + 2);

        const uint32_t bo = (uint32_t)(it % 3) * BUFB;
#pragma unroll
        for (int ks = 0; ks < 2; ks++) {
            const uint32_t ko = bo + ks * 32;   // 8 floats = 32 bytes
            uint32_t af[4][4];
#pragma unroll
            for (int i = 0; i < 4; i++)
                ldsm4(af[i], aBase + i * ROWSKIP + ko);
            if (DO_CVT) {
#pragma unroll
                for (int i = 0; i < 4; i++)
#pragma unroll
                    for (int q = 0; q < 4; q++) af[i][q] = f2tf_u(af[i][q]);
            }
#pragma unroll
            for (int p = 0; p < 2; p++) {
                uint32_t bf[4];
                ldsm4(bf, bBase + p * ROWSKIP + ko);
#pragma unroll
                for (int i = 0; i < 4; i++) {
                    mma_tf32(c[i][2 * p],     af[i], &bf[0]);
                    mma_tf32(c[i][2 * p + 1], af[i], &bf[2]);
                }
            }
        }
    }

    float invf[4];
    if (do_rope) {
#pragma unroll
        for (int j = 0; j < 4; j++) {
            int cg = col0 + warpN + j * 8 + 2 * t;
            int ii = (cg & (HEAD_DIM - 1)) >> 1;
            invf[j] = expf(-0.287823137f * (float)ii);   // ln(1e4)/32
        }
    }
#pragma unroll
    for (int i = 0; i < 4; i++) {
        const int r0 = row0 + warpM + i * 16 + g;
        const int r1 = r0 + 8;
        float p0 = 0.f, p1 = 0.f;
        if (do_rope) { p0 = (float)pos[r0]; p1 = (float)pos[r1]; }
#pragma unroll
        for (int j = 0; j < 4; j++) {
            const int cg = col0 + warpN + j * 8 + 2 * t;
            const float b0 = bias[cg], b1 = bias[cg + 1];
            float x0 = c[i][j][0] + b0, x1 = c[i][j][1] + b1;
            float y0 = c[i][j][2] + b0, y1 = c[i][j][3] + b1;
            if (do_rope) {
                float sn, cs;
                sincosf(p0 * invf[j], &sn, &cs);
                float t0 = x0 * cs - x1 * sn, t1 = x0 * sn + x1 * cs;
                x0 = t0; x1 = t1;
                sincosf(p1 * invf[j], &sn, &cs);
                t0 = y0 * cs - y1 * sn; t1 = y0 * sn + y1 * cs;
                y0 = t0; y1 = t1;
            }
            if (do_round) {
                x0 = f2tf_f(x0 * oscale); x1 = f2tf_f(x1 * oscale);
                y0 = f2tf_f(y0 * oscale); y1 = f2tf_f(y1 * oscale);
            }
            *(float2*)&out[(size_t)r0 * D_MODEL + cg] = make_float2(x0, x1);
            *(float2*)&out[(size_t)r1 * D_MODEL + cg] = make_float2(y0, y1);
        }
    }
}

// Fused Q/K/V projection: grid.z selects input/weight/bias/output.
// Outputs tf32-rounded; Q additionally scaled by 0.125 (exact).
__global__ void __launch_bounds__(256, 3) gemm_qkv(
    const float* __restrict__ query, const float* __restrict__ key_,
    const float* __restrict__ value, const float* __restrict__ wtbase,
    const float* __restrict__ b_q, const float* __restrict__ b_k,
    const float* __restrict__ b_v, const int* __restrict__ pos,
    float* __restrict__ oQ, float* __restrict__ oK, float* __restrict__ oV)
{
    extern __shared__ float gsm[];
    const int z = blockIdx.z;
    const float* X    = (z == 0) ? query : (z == 1) ? key_ : value;
    const float* WT   = wtbase + (size_t)z * D_MODEL * D_MODEL;
    const float* bias = (z == 0) ? b_q : (z == 1) ? b_k : b_v;
    float* out        = (z == 0) ? oQ : (z == 1) ? oK : oV;
    gemm_body<1>(X, WT, bias, pos, out, z < 2, true,
                 (z == 0) ? 0.125f : 1.0f,
                 gsm, gsm + 3 * BUFF, blockIdx.y * 128, blockIdx.x * 128);
}

// Output projection: A (g_O) already tf32-rounded by attention; no out-round.
__global__ void __launch_bounds__(256, 3) gemm_o(
    const float* __restrict__ X, const float* __restrict__ WT,
    const float* __restrict__ bias, float* __restrict__ out)
{
    extern __shared__ float gsm[];
    gemm_body<0>(X, WT, bias, nullptr, out, false, false, 1.0f,
                 gsm, gsm + 3 * BUFF, blockIdx.y * 128, blockIdx.x * 128);
}

// ===========================================================================
// Flash attention, causal — tf32 mma for S=QK^T and O=PV.
// 128 threads (4 warps); 64x64 tiles; Q/K/V pre-rounded+scaled by producer,
// cp.async loads, SINGLE K/V buffer -> 69.6KB smem -> 3 CTAs/SM.
// ===========================================================================
#define ASTR 68
#define KVF  (64 * ASTR)                 // floats per tile buffer
static constexpr int ATTN_SMEM_BYTES = 4 * KVF * 4;   // Q + K + V + P = 69632

__global__ void __launch_bounds__(128) attn_kernel()
{
    extern __shared__ float smf[];
    float* Qs = smf;                 // [64][ASTR]
    float* Ks = Qs + KVF;
    float* Vs = Ks + KVF;
    float* Ps = Vs + KVF;            // per-warp 16-row regions

    const int tid   = threadIdx.x;
    const int w     = tid >> 5, lane = tid & 31;
    const int g     = lane >> 2, t = lane & 3;
    const int qtile = blockIdx.x;
    const int h     = blockIdx.y;
    const int b     = blockIdx.z;
    const int qrow0 = b * SEQ + qtile * 64;
    const int cb    = h * HEAD_DIM;

    auto stage_kv = [&](int kt) {
        const int krow0 = b * SEQ + kt * 64;
#pragma unroll
        for (int itr = 0; itr < 8; itr++) {
            int e = itr * 128 + tid;
            int r = e >> 4, c = (e & 15) * 4;
            cp_async16(smem_u32(&Ks[r * ASTR + c]),
                       &g_K[(size_t)(krow0 + r) * D_MODEL + cb + c]);
            cp_async16(smem_u32(&Vs[r * ASTR + c]),
                       &g_V[(size_t)(krow0 + r) * D_MODEL + cb + c]);
        }
        cp_commit();
    };

    // prologue: Q + first K/V tile
#pragma unroll
    for (int itr = 0; itr < 8; itr++) {
        int e = itr * 128 + tid;
        int r = e >> 4, c = (e & 15) * 4;
        cp_async16(smem_u32(&Qs[r * ASTR + c]),
                   &g_Q[(size_t)(qrow0 + r) * D_MODEL + cb + c]);
    }
    stage_kv(0);

    const uint32_t aQ = smem_u32(&Qs[(w * 16 + (lane & 15)) * ASTR + (lane >> 4) * 4]);
    const uint32_t aP = smem_u32(&Ps[(w * 16 + (lane & 15)) * ASTR + (lane >> 4) * 4]);
    uint32_t bK[4];
#pragma unroll
    for (int p = 0; p < 4; p++)
        bK[p] = smem_u32(&Ks[((2 * p + (lane >> 4)) * 8 + (lane & 7)) * ASTR +
                             ((lane >> 3) & 1) * 4]);

    float cO[8][4];
#pragma unroll
    for (int j = 0; j < 8; j++)
#pragma unroll
        for (int q = 0; q < 4; q++) cO[j][q] = 0.f;
    float m0 = -1e30f, m1 = -1e30f, l0 = 0.f, l1 = 0.f;

    const int q0 = w * 16 + g;
    const int q1 = q0 + 8;

#pragma unroll 1
    for (int kt = 0; kt <= qtile; kt++) {
        cp_wait<0>();
        __syncthreads();   // K/V(kt) visible to all

        // ---- S = Q @ K^T  (Q pre-scaled by 1/8) ----
        float cS[8][4];
#pragma unroll
        for (int j = 0; j < 8; j++)
#pragma unroll
            for (int q = 0; q < 4; q++) cS[j][q] = 0.f;
#pragma unroll
        for (int ks = 0; ks < 8; ks++) {
            uint32_t af[4], bf[4][4];
            ldsm4(af, aQ + ks * 32);
#pragma unroll
            for (int p = 0; p < 4; p++) ldsm4(bf[p], bK[p] + ks * 32);
#pragma unroll
            for (int j = 0; j < 8; j++)
                mma_tf32(cS[j], af, &bf[j >> 1][(j & 1) * 2]);
        }

        if (kt == qtile) {
#pragma unroll
            for (int j = 0; j < 8; j++) {
                int kp = j * 8 + 2 * t;
                if (kp     > q0) cS[j][0] = -1e30f;
                if (kp + 1 > q0) cS[j][1] = -1e30f;
                if (kp     > q1) cS[j][2] = -1e30f;
                if (kp + 1 > q1) cS[j][3] = -1e30f;
            }
        }

        // ---- online softmax ----
        float mt0 = -1e30f, mt1 = -1e30f;
#pragma unroll
        for (int j = 0; j < 8; j++) {
            mt0 = fmaxf(mt0, fmaxf(cS[j][0], cS[j][1]));
            mt1 = fmaxf(mt1, fmaxf(cS[j][2], cS[j][3]));
        }
        mt0 = fmaxf(mt0, __shfl_xor_sync(0xffffffffu, mt0, 1));
        mt0 = fmaxf(mt0, __shfl_xor_sync(0xffffffffu, mt0, 2));
        mt1 = fmaxf(mt1, __shfl_xor_sync(0xffffffffu, mt1, 1));
        mt1 = fmaxf(mt1, __shfl_xor_sync(0xffffffffu, mt1, 2));
        const float mn0 = fmaxf(m0, mt0), mn1 = fmaxf(m1, mt1);
        const float f0 = __expf(m0 - mn0), f1 = __expf(m1 - mn1);
        float s0 = 0.f, s1 = 0.f;
#pragma unroll
        for (int j = 0; j < 8; j++) {
            cS[j][0] = __expf(cS[j][0] - mn0); s0 += cS[j][0];
            cS[j][1] = __expf(cS[j][1] - mn0); s0 += cS[j][1];
            cS[j][2] = __expf(cS[j][2] - mn1); s1 += cS[j][2];
            cS[j][3] = __expf(cS[j][3] - mn1); s1 += cS[j][3];
        }
        s0 += __shfl_xor_sync(0xffffffffu, s0, 1);
        s0 += __shfl_xor_sync(0xffffffffu, s0, 2);
        s1 += __shfl_xor_sync(0xffffffffu, s1, 1);
        s1 += __shfl_xor_sync(0xffffffffu, s1, 2);
        l0 = l0 * f0 + s0;  l1 = l1 * f1 + s1;
        m0 = mn0;           m1 = mn1;
#pragma unroll
        for (int j = 0; j < 8; j++) {
            cO[j][0] *= f0; cO[j][1] *= f0;
            cO[j][2] *= f1; cO[j][3] *= f1;
        }

        // ---- P to per-warp smem (tf32-rounded) ----
#pragma unroll
        for (int j = 0; j < 8; j++) {
            *(float2*)&Ps[q0 * ASTR + j * 8 + 2 * t] =
                make_float2(f2tf_f(cS[j][0]), f2tf_f(cS[j][1]));
            *(float2*)&Ps[q1 * ASTR + j * 8 + 2 * t] =
                make_float2(f2tf_f(cS[j][2]), f2tf_f(cS[j][3]));
        }
        __syncwarp();

        // ---- O += P @ V ----
#pragma unroll
        for (int ks = 0; ks < 8; ks++) {
            uint32_t ap[4];
            ldsm4(ap, aP + ks * 32);
            const float* vb = &Vs[(ks * 8 + t) * ASTR + g];
#pragma unroll
            for (int j = 0; j < 8; j++) {
                uint32_t bv[2];
                bv[0] = __float_as_uint(vb[j * 8]);
                bv[1] = __float_as_uint(vb[4 * ASTR + j * 8]);
                mma_tf32(cO[j], ap, bv);
            }
        }

        __syncthreads();   // all warps done reading K/V before restage
        if (kt + 1 <= qtile) stage_kv(kt + 1);
    }

    // ---- epilogue: normalize, round (feeds gemm_o), store ----
    const float inv0 = 1.f / l0, inv1 = 1.f / l1;
    float* dst0 = &g_O[(size_t)(qrow0 + q0) * D_MODEL + cb];
    float* dst1 = &g_O[(size_t)(qrow0 + q1) * D_MODEL + cb];
#pragma unroll
    for (int j = 0; j < 8; j++) {
        *(float2*)&dst0[j * 8 + 2 * t] =
            make_float2(f2tf_f(cO[j][0] * inv0), f2tf_f(cO[j][1] * inv0));
        *(float2*)&dst1[j * 8 + 2 * t] =
            make_float2(f2tf_f(cO[j][2] * inv1), f2tf_f(cO[j][3] * inv1));
    }
}

// ---------------------------------------------------------------------------
extern "C" void kernel_launch(void* const* d_in, const int* in_sizes, int n_in,
                              void* d_out, int out_size)
{
    (void)in_sizes; (void)n_in; (void)out_size;
    const float* query = (const float*)d_in[0];
    const float* key_  = (const float*)d_in[1];
    const float* value = (const float*)d_in[2];
    const int*   pos   = (const int*)d_in[3];
    const float* w_q   = (const float*)d_in[4];
    const float* b_q   = (const float*)d_in[5];
    const float* w_k   = (const float*)d_in[6];
    const float* b_k   = (const float*)d_in[7];
    const float* w_v   = (const float*)d_in[8];
    const float* b_v   = (const float*)d_in[9];
    const float* w_o   = (const float*)d_in[10];
    const float* b_o   = (const float*)d_in[11];
    float* out = (float*)d_out;

    float *pQ, *pK, *pV, *pO, *pWT;
    cudaGetSymbolAddress((void**)&pQ, g_Q);
    cudaGetSymbolAddress((void**)&pK, g_K);
    cudaGetSymbolAddress((void**)&pV, g_V);
    cudaGetSymbolAddress((void**)&pO, g_O);
    cudaGetSymbolAddress((void**)&pWT, g_WT);
    float* wto = pWT + 3 * (size_t)D_MODEL * D_MODEL;

    cudaFuncSetAttribute(attn_kernel,
                         cudaFuncAttributeMaxDynamicSharedMemorySize,
                         ATTN_SMEM_BYTES);
    cudaFuncSetAttribute(gemm_qkv,
                         cudaFuncAttributeMaxDynamicSharedMemorySize, GEMM_SMEM);
    cudaFuncSetAttribute(gemm_o,
                         cudaFuncAttributeMaxDynamicSharedMemorySize, GEMM_SMEM);

    transpose_kernel<<<dim3(32, 32, 4), dim3(32, 8)>>>(w_q, w_k, w_v, w_o, pWT);

    gemm_qkv<<<dim3(D_MODEL / 128, ROWS / 128, 3), 256, GEMM_SMEM>>>(
        query, key_, value, pWT, b_q, b_k, b_v, pos, pQ, pK, pV);

    attn_kernel<<<dim3(SEQ / 64, NUM_HEADS, BATCH), 128, ATTN_SMEM_BYTES>>>();

    gemm_o<<<dim3(D_MODEL / 128, ROWS / 128), 256, GEMM_SMEM>>>(pO, wto, b_o, out);
}

// round 16
// speedup vs baseline: 1.4136x; 1.4136x over previous
#include <cuda_runtime.h>
#include <math.h>
#include <cstdint>

#define D_MODEL   1024
#define NUM_HEADS 16
#define HEAD_DIM  64
#define BATCH     4
#define SEQ       2048
#define ROWS      (BATCH * SEQ)   // 8192

// Scratch (allocation-free rule: __device__ globals)
__device__ float g_Q[ROWS * D_MODEL];
__device__ float g_K[ROWS * D_MODEL];
__device__ float g_V[ROWS * D_MODEL];
__device__ float g_O[ROWS * D_MODEL];
__device__ float g_WT[4 * D_MODEL * D_MODEL];   // transposed+rounded weights

// ===========================================================================
// Helpers (arch-agnostic PTX only: cp.async + ldmatrix + mma.sync tf32)
// ===========================================================================
__device__ __forceinline__ uint32_t smem_u32(const void* p) {
    uint32_t a;
    asm("{ .reg .u64 t; cvta.to.shared.u64 t, %1; cvt.u32.u64 %0, t; }"
        : "=r"(a) : "l"(p));
    return a;
}
__device__ __forceinline__ void cp_async16(uint32_t dst, const void* src) {
    asm volatile("cp.async.cg.shared.global [%0], [%1], 16;"
                 :: "r"(dst), "l"(src) : "memory");
}
__device__ __forceinline__ void cp_commit() {
    asm volatile("cp.async.commit_group;" ::: "memory");
}
template <int N>
__device__ __forceinline__ void cp_wait() {
    asm volatile("cp.async.wait_group %0;" :: "n"(N) : "memory");
}
__device__ __forceinline__ float f2tf_f(float x) {
    uint32_t r;
    asm("cvt.rna.tf32.f32 %0, %1;" : "=r"(r) : "f"(x));
    return __uint_as_float(r);
}
__device__ __forceinline__ uint32_t f2tf_u(uint32_t x) {
    uint32_t r;
    asm("cvt.rna.tf32.f32 %0, %1;" : "=r"(r) : "r"(x));
    return r;
}
__device__ __forceinline__ void ldsm4(uint32_t* r, uint32_t addr) {
    asm volatile("ldmatrix.sync.aligned.m8n8.x4.shared.b16 {%0,%1,%2,%3}, [%4];"
                 : "=r"(r[0]), "=r"(r[1]), "=r"(r[2]), "=r"(r[3]) : "r"(addr));
}
__device__ __forceinline__ void mma_tf32(float* c, const uint32_t* a,
                                         const uint32_t* b) {
    asm volatile(
        "mma.sync.aligned.m16n8k8.row.col.f32.tf32.tf32.f32 "
        "{%0,%1,%2,%3}, {%4,%5,%6,%7}, {%8,%9}, {%0,%1,%2,%3};"
        : "+f"(c[0]), "+f"(c[1]), "+f"(c[2]), "+f"(c[3])
        : "r"(a[0]), "r"(a[1]), "r"(a[2]), "r"(a[3]), "r"(b[0]), "r"(b[1]));
}

// ===========================================================================
// Fused weight transpose + tf32 round: WT_z[n][k] = round(W_z[k][n]), z=0..3
// ===========================================================================
__global__ void __launch_bounds__(256) transpose_kernel(
    const float* __restrict__ w0, const float* __restrict__ w1,
    const float* __restrict__ w2, const float* __restrict__ w3,
    float* __restrict__ outbase)
{
    __shared__ float t[32][33];
    const int z = blockIdx.z;
    const float* in = (z == 0) ? w0 : (z == 1) ? w1 : (z == 2) ? w2 : w3;
    float* out = outbase + (size_t)z * D_MODEL * D_MODEL;
    const int bx = blockIdx.x * 32, by = blockIdx.y * 32;
#pragma unroll
    for (int i = threadIdx.y; i < 32; i += 8)
        t[i][threadIdx.x] = f2tf_f(in[(size_t)(by + i) * D_MODEL + bx + threadIdx.x]);
    __syncthreads();
#pragma unroll
    for (int i = threadIdx.y; i < 32; i += 8)
        out[(size_t)(bx + i) * D_MODEL + by + threadIdx.x] = t[threadIdx.x][i];
}

// ===========================================================================
// TF32 mma.sync GEMM core. CTA 128x128, BK=32, 8 warps, warp 64x32.
// 2-stage cp.async double buffer (R13-proven sync structure), SSTR=36
// (12.5% padding vs 25% at BK=16; rows step 4 banks -> ldsm conflict-free).
// ===========================================================================
#define BK      32
#define SSTR    36
#define NKIT    (D_MODEL / BK)        // 32
#define BUFF    (128 * SSTR)          // floats per buffer (4608)
#define BUFB    (BUFF * 4)            // bytes per buffer (18432)
static constexpr int GEMM_SMEM = 4 * BUFB;   // 2 stages x (A+B) = 73728 B

template <int DO_CVT>
__device__ __forceinline__ void gemm_body(
    const float* __restrict__ X, const float* __restrict__ WT,
    const float* __restrict__ bias, const int* __restrict__ pos,
    float* __restrict__ out, bool do_rope, bool do_round, float oscale,
    float* __restrict__ As, float* __restrict__ Bs,
    int row0, int col0)
{
    const int tid  = threadIdx.x;
    const int wid  = tid >> 5, lane = tid & 31;
    const int g    = lane >> 2;
    const int t    = lane & 3;
    const int warpM = (wid >> 2) * 64;
    const int warpN = (wid & 3) * 32;

    const int arow = lane & 15, acolh = (lane >> 4) * 4;
    uint32_t aAddr[4];
#pragma unroll
    for (int i = 0; i < 4; i++)
        aAddr[i] = smem_u32(&As[(warpM + i * 16 + arow) * SSTR + acolh]);
    const int brow = lane & 7, bjh = lane >> 4, bcolh = ((lane >> 3) & 1) * 4;
    uint32_t bAddr[2];
#pragma unroll
    for (int p = 0; p < 2; p++)
        bAddr[p] = smem_u32(&Bs[(warpN + (2 * p + bjh) * 8 + brow) * SSTR + bcolh]);

    float c[4][4][4];
#pragma unroll
    for (int i = 0; i < 4; i++)
#pragma unroll
        for (int j = 0; j < 4; j++)
#pragma unroll
            for (int q = 0; q < 4; q++) c[i][j][q] = 0.f;

    auto stage = [&](int buf, int it) {
        const float* aSrc = X  + (size_t)row0 * D_MODEL + it * BK;
        const float* bSrc = WT + (size_t)col0 * D_MODEL + it * BK;
#pragma unroll
        for (int rep = 0; rep < 4; rep++) {
            int idx = rep * 256 + tid;          // 0..1023
            int r = idx >> 3, c4 = (idx & 7) * 4;
            cp_async16(smem_u32(&As[buf * BUFF + r * SSTR + c4]),
                       aSrc + (size_t)r * D_MODEL + c4);
            cp_async16(smem_u32(&Bs[buf * BUFF + r * SSTR + c4]),
                       bSrc + (size_t)r * D_MODEL + c4);
        }
        cp_commit();
    };

    stage(0, 0);

#pragma unroll 1
    for (int it = 0; it < NKIT; it++) {
        const int buf = it & 1;
        if (it + 1 < NKIT) {
            stage(buf ^ 1, it + 1);
            cp_wait<1>();
        } else {
            cp_wait<0>();
        }
        __syncthreads();

        const uint32_t bo = (uint32_t)buf * BUFB;
#pragma unroll
        for (int ks = 0; ks < 4; ks++) {
            const uint32_t ko = bo + ks * 32;   // 8 floats = 32 bytes
            uint32_t af[4][4], bf[2][4];
#pragma unroll
            for (int i = 0; i < 4; i++) ldsm4(af[i], aAddr[i] + ko);
#pragma unroll
            for (int p = 0; p < 2; p++) ldsm4(bf[p], bAddr[p] + ko);
            if (DO_CVT) {
#pragma unroll
                for (int i = 0; i < 4; i++)
#pragma unroll
                    for (int q = 0; q < 4; q++) af[i][q] = f2tf_u(af[i][q]);
            }
#pragma unroll
            for (int i = 0; i < 4; i++)
#pragma unroll
                for (int j = 0; j < 4; j++)
                    mma_tf32(c[i][j], af[i], &bf[j >> 1][(j & 1) * 2]);
        }
        __syncthreads();
    }

    float invf[4];
    if (do_rope) {
#pragma unroll
        for (int j = 0; j < 4; j++) {
            int cg = col0 + warpN + j * 8 + 2 * t;
            int ii = (cg & (HEAD_DIM - 1)) >> 1;
            invf[j] = expf(-0.287823137f * (float)ii);   // ln(1e4)/32
        }
    }
#pragma unroll
    for (int i = 0; i < 4; i++) {
        const int r0 = row0 + warpM + i * 16 + g;
        const int r1 = r0 + 8;
        float p0 = 0.f, p1 = 0.f;
        if (do_rope) { p0 = (float)pos[r0]; p1 = (float)pos[r1]; }
#pragma unroll
        for (int j = 0; j < 4; j++) {
            const int cg = col0 + warpN + j * 8 + 2 * t;
            const float b0 = bias[cg], b1 = bias[cg + 1];
            float x0 = c[i][j][0] + b0, x1 = c[i][j][1] + b1;
            float y0 = c[i][j][2] + b0, y1 = c[i][j][3] + b1;
            if (do_rope) {
                float sn, cs;
                sincosf(p0 * invf[j], &sn, &cs);
                float t0 = x0 * cs - x1 * sn, t1 = x0 * sn + x1 * cs;
                x0 = t0; x1 = t1;
                sincosf(p1 * invf[j], &sn, &cs);
                t0 = y0 * cs - y1 * sn; t1 = y0 * sn + y1 * cs;
                y0 = t0; y1 = t1;
            }
            if (do_round) {
                x0 = f2tf_f(x0 * oscale); x1 = f2tf_f(x1 * oscale);
                y0 = f2tf_f(y0 * oscale); y1 = f2tf_f(y1 * oscale);
            }
            *(float2*)&out[(size_t)r0 * D_MODEL + cg] = make_float2(x0, x1);
            *(float2*)&out[(size_t)r1 * D_MODEL + cg] = make_float2(y0, y1);
        }
    }
}

// Fused Q/K/V projection: grid.z selects input/weight/bias/output.
// Outputs tf32-rounded; Q additionally scaled by 0.125 (exact).
__global__ void __launch_bounds__(256) gemm_qkv(
    const float* __restrict__ query, const float* __restrict__ key_,
    const float* __restrict__ value, const float* __restrict__ wtbase,
    const float* __restrict__ b_q, const float* __restrict__ b_k,
    const float* __restrict__ b_v, const int* __restrict__ pos,
    float* __restrict__ oQ, float* __restrict__ oK, float* __restrict__ oV)
{
    extern __shared__ float gsm[];
    const int z = blockIdx.z;
    const float* X    = (z == 0) ? query : (z == 1) ? key_ : value;
    const float* WT   = wtbase + (size_t)z * D_MODEL * D_MODEL;
    const float* bias = (z == 0) ? b_q : (z == 1) ? b_k : b_v;
    float* out        = (z == 0) ? oQ : (z == 1) ? oK : oV;
    gemm_body<1>(X, WT, bias, pos, out, z < 2, true,
                 (z == 0) ? 0.125f : 1.0f,
                 gsm, gsm + 2 * BUFF, blockIdx.y * 128, blockIdx.x * 128);
}

// Output projection: A (g_O) already tf32-rounded by attention; no out-round.
__global__ void __launch_bounds__(256) gemm_o(
    const float* __restrict__ X, const float* __restrict__ WT,
    const float* __restrict__ bias, float* __restrict__ out)
{
    extern __shared__ float gsm[];
    gemm_body<0>(X, WT, bias, nullptr, out, false, false, 1.0f,
                 gsm, gsm + 2 * BUFF, blockIdx.y * 128, blockIdx.x * 128);
}

// ===========================================================================
// Flash attention, causal — tf32 mma for S=QK^T and O=PV.  (R14-proven)
// 128 threads (4 warps); 64x64 tiles; Q/K/V pre-rounded+scaled by producer,
// cp.async loads with double-buffered K/V.
// ===========================================================================
#define ASTR 68
#define KVF  (64 * ASTR)                 // floats per tile buffer
#define KVB  (KVF * 4)                   // bytes per tile buffer
static constexpr int ATTN_SMEM_BYTES = 6 * KVB;   // Q + 2K + 2V + P = 104448

__global__ void __launch_bounds__(128) attn_kernel()
{
    extern __shared__ float smf[];
    float* Qs = smf;                 // [64][ASTR]
    float* Ks = Qs + KVF;            // 2 buffers
    float* Vs = Ks + 2 * KVF;        // 2 buffers
    float* Ps = Vs + 2 * KVF;        // per-warp 16-row regions

    const int tid   = threadIdx.x;
    const int w     = tid >> 5, lane = tid & 31;
    const int g     = lane >> 2, t = lane & 3;
    const int qtile = blockIdx.x;
    const int h     = blockIdx.y;
    const int b     = blockIdx.z;
    const int qrow0 = b * SEQ + qtile * 64;
    const int cb    = h * HEAD_DIM;

    auto stage_kv = [&](int buf, int kt) {
        const int krow0 = b * SEQ + kt * 64;
#pragma unroll
        for (int itr = 0; itr < 8; itr++) {
            int e = itr * 128 + tid;
            int r = e >> 4, c = (e & 15) * 4;
            cp_async16(smem_u32(&Ks[buf * KVF + r * ASTR + c]),
                       &g_K[(size_t)(krow0 + r) * D_MODEL + cb + c]);
            cp_async16(smem_u32(&Vs[buf * KVF + r * ASTR + c]),
                       &g_V[(size_t)(krow0 + r) * D_MODEL + cb + c]);
        }
    };

    // prologue: Q + first K/V tile as one group
#pragma unroll
    for (int itr = 0; itr < 8; itr++) {
        int e = itr * 128 + tid;
        int r = e >> 4, c = (e & 15) * 4;
        cp_async16(smem_u32(&Qs[r * ASTR + c]),
                   &g_Q[(size_t)(qrow0 + r) * D_MODEL + cb + c]);
    }
    stage_kv(0, 0);
    cp_commit();

    const uint32_t aQ = smem_u32(&Qs[(w * 16 + (lane & 15)) * ASTR + (lane >> 4) * 4]);
    const uint32_t aP = smem_u32(&Ps[(w * 16 + (lane & 15)) * ASTR + (lane >> 4) * 4]);
    uint32_t bK[4];
#pragma unroll
    for (int p = 0; p < 4; p++)
        bK[p] = smem_u32(&Ks[((2 * p + (lane >> 4)) * 8 + (lane & 7)) * ASTR +
                             ((lane >> 3) & 1) * 4]);

    float cO[8][4];
#pragma unroll
    for (int j = 0; j < 8; j++)
#pragma unroll
        for (int q = 0; q < 4; q++) cO[j][q] = 0.f;
    float m0 = -1e30f, m1 = -1e30f, l0 = 0.f, l1 = 0.f;

    const int q0 = w * 16 + g;
    const int q1 = q0 + 8;

#pragma unroll 1
    for (int kt = 0; kt <= qtile; kt++) {
        __syncthreads();   // all threads done reading buf (kt+1)&1 from iter kt-1
        if (kt + 1 <= qtile) {
            stage_kv((kt + 1) & 1, kt + 1);
            cp_commit();
            cp_wait<1>();
        } else {
            cp_wait<0>();
        }
        __syncthreads();   // data for tile kt visible to all

        const uint32_t kvbo = (uint32_t)(kt & 1) * KVB;

        // ---- S = Q @ K^T  (Q pre-scaled by 1/8) ----
        float cS[8][4];
#pragma unroll
        for (int j = 0; j < 8; j++)
#pragma unroll
            for (int q = 0; q < 4; q++) cS[j][q] = 0.f;
#pragma unroll
        for (int ks = 0; ks < 8; ks++) {
            uint32_t af[4], bf[4][4];
            ldsm4(af, aQ + ks * 32);
#pragma unroll
            for (int p = 0; p < 4; p++) ldsm4(bf[p], bK[p] + kvbo + ks * 32);
#pragma unroll
            for (int j = 0; j < 8; j++)
                mma_tf32(cS[j], af, &bf[j >> 1][(j & 1) * 2]);
        }

        if (kt == qtile) {
#pragma unroll
            for (int j = 0; j < 8; j++) {
                int kp = j * 8 + 2 * t;
                if (kp     > q0) cS[j][0] = -1e30f;
                if (kp + 1 > q0) cS[j][1] = -1e30f;
                if (kp     > q1) cS[j][2] = -1e30f;
                if (kp + 1 > q1) cS[j][3] = -1e30f;
            }
        }

        // ---- online softmax ----
        float mt0 = -1e30f, mt1 = -1e30f;
#pragma unroll
        for (int j = 0; j < 8; j++) {
            mt0 = fmaxf(mt0, fmaxf(cS[j][0], cS[j][1]));
            mt1 = fmaxf(mt1, fmaxf(cS[j][2], cS[j][3]));
        }
        mt0 = fmaxf(mt0, __shfl_xor_sync(0xffffffffu, mt0, 1));
        mt0 = fmaxf(mt0, __shfl_xor_sync(0xffffffffu, mt0, 2));
        mt1 = fmaxf(mt1, __shfl_xor_sync(0xffffffffu, mt1, 1));
        mt1 = fmaxf(mt1, __shfl_xor_sync(0xffffffffu, mt1, 2));
        const float mn0 = fmaxf(m0, mt0), mn1 = fmaxf(m1, mt1);
        const float f0 = __expf(m0 - mn0), f1 = __expf(m1 - mn1);
        float s0 = 0.f, s1 = 0.f;
#pragma unroll
        for (int j = 0; j < 8; j++) {
            cS[j][0] = __expf(cS[j][0] - mn0); s0 += cS[j][0];
            cS[j][1] = __expf(cS[j][1] - mn0); s0 += cS[j][1];
            cS[j][2] = __expf(cS[j][2] - mn1); s1 += cS[j][2];
            cS[j][3] = __expf(cS[j][3] - mn1); s1 += cS[j][3];
        }
        s0 += __shfl_xor_sync(0xffffffffu, s0, 1);
        s0 += __shfl_xor_sync(0xffffffffu, s0, 2);
        s1 += __shfl_xor_sync(0xffffffffu, s1, 1);
        s1 += __shfl_xor_sync(0xffffffffu, s1, 2);
        l0 = l0 * f0 + s0;  l1 = l1 * f1 + s1;
        m0 = mn0;           m1 = mn1;
#pragma unroll
        for (int j = 0; j < 8; j++) {
            cO[j][0] *= f0; cO[j][1] *= f0;
            cO[j][2] *= f1; cO[j][3] *= f1;
        }

        // ---- P to per-warp smem (tf32-rounded) ----
#pragma unroll
        for (int j = 0; j < 8; j++) {
            *(float2*)&Ps[q0 * ASTR + j * 8 + 2 * t] =
                make_float2(f2tf_f(cS[j][0]), f2tf_f(cS[j][1]));
            *(float2*)&Ps[q1 * ASTR + j * 8 + 2 * t] =
                make_float2(f2tf_f(cS[j][2]), f2tf_f(cS[j][3]));
        }
        __syncwarp();

        // ---- O += P @ V ----
#pragma unroll
        for (int ks = 0; ks < 8; ks++) {
            uint32_t ap[4];
            ldsm4(ap, aP + ks * 32);
            const float* vb = &Vs[(kt & 1) * KVF + (ks * 8 + t) * ASTR + g];
#pragma unroll
            for (int j = 0; j < 8; j++) {
                uint32_t bv[2];
                bv[0] = __float_as_uint(vb[j * 8]);
                bv[1] = __float_as_uint(vb[4 * ASTR + j * 8]);
                mma_tf32(cO[j], ap, bv);
            }
        }
    }

    // ---- epilogue: normalize, round (feeds gemm_o), store ----
    const float inv0 = 1.f / l0, inv1 = 1.f / l1;
    float* dst0 = &g_O[(size_t)(qrow0 + q0) * D_MODEL + cb];
    float* dst1 = &g_O[(size_t)(qrow0 + q1) * D_MODEL + cb];
#pragma unroll
    for (int j = 0; j < 8; j++) {
        *(float2*)&dst0[j * 8 + 2 * t] =
            make_float2(f2tf_f(cO[j][0] * inv0), f2tf_f(cO[j][1] * inv0));
        *(float2*)&dst1[j * 8 + 2 * t] =
            make_float2(f2tf_f(cO[j][2] * inv1), f2tf_f(cO[j][3] * inv1));
    }
}

// ---------------------------------------------------------------------------
extern "C" void kernel_launch(void* const* d_in, const int* in_sizes, int n_in,
                              void* d_out, int out_size)
{
    (void)in_sizes; (void)n_in; (void)out_size;
    const float* query = (const float*)d_in[0];
    const float* key_  = (const float*)d_in[1];
    const float* value = (const float*)d_in[2];
    const int*   pos   = (const int*)d_in[3];
    const float* w_q   = (const float*)d_in[4];
    const float* b_q   = (const float*)d_in[5];
    const float* w_k   = (const float*)d_in[6];
    const float* b_k   = (const float*)d_in[7];
    const float* w_v   = (const float*)d_in[8];
    const float* b_v   = (const float*)d_in[9];
    const float* w_o   = (const float*)d_in[10];
    const float* b_o   = (const float*)d_in[11];
    float* out = (float*)d_out;

    float *pQ, *pK, *pV, *pO, *pWT;
    cudaGetSymbolAddress((void**)&pQ, g_Q);
    cudaGetSymbolAddress((void**)&pK, g_K);
    cudaGetSymbolAddress((void**)&pV, g_V);
    cudaGetSymbolAddress((void**)&pO, g_O);
    cudaGetSymbolAddress((void**)&pWT, g_WT);
    float* wto = pWT + 3 * (size_t)D_MODEL * D_MODEL;

    cudaFuncSetAttribute(attn_kernel,
                         cudaFuncAttributeMaxDynamicSharedMemorySize,
                         ATTN_SMEM_BYTES);
    cudaFuncSetAttribute(gemm_qkv,
                         cudaFuncAttributeMaxDynamicSharedMemorySize, GEMM_SMEM);
    cudaFuncSetAttribute(gemm_o,
                         cudaFuncAttributeMaxDynamicSharedMemorySize, GEMM_SMEM);

    transpose_kernel<<<dim3(32, 32, 4), dim3(32, 8)>>>(w_q, w_k, w_v, w_o, pWT);

    gemm_qkv<<<dim3(D_MODEL / 128, ROWS / 128, 3), 256, GEMM_SMEM>>>(
        query, key_, value, pWT, b_q, b_k, b_v, pos, pQ, pK, pV);

    attn_kernel<<<dim3(SEQ / 64, NUM_HEADS, BATCH), 128, ATTN_SMEM_BYTES>>>();

    gemm_o<<<dim3(D_MODEL / 128, ROWS / 128), 256, GEMM_SMEM>>>(pO, wto, b_o, out);
}

// round 17
// speedup vs baseline: 1.4597x; 1.0326x over previous
#include <cuda_runtime.h>
#include <math.h>
#include <cstdint>

#define D_MODEL   1024
#define NUM_HEADS 16
#define HEAD_DIM  64
#define BATCH     4
#define SEQ       2048
#define ROWS      (BATCH * SEQ)   // 8192
#define NQT       (SEQ / 64)      // 32 q-tiles

// Scratch (allocation-free rule: __device__ globals)
__device__ float g_Q[ROWS * D_MODEL];
__device__ float g_K[ROWS * D_MODEL];
__device__ float g_V[ROWS * D_MODEL];
__device__ float g_O[ROWS * D_MODEL];
__device__ float g_WT[4 * D_MODEL * D_MODEL];   // transposed+rounded weights

// ===========================================================================
// Helpers (arch-agnostic PTX only: cp.async + ldmatrix + mma.sync tf32)
// ===========================================================================
__device__ __forceinline__ uint32_t smem_u32(const void* p) {
    uint32_t a;
    asm("{ .reg .u64 t; cvta.to.shared.u64 t, %1; cvt.u32.u64 %0, t; }"
        : "=r"(a) : "l"(p));
    return a;
}
__device__ __forceinline__ void cp_async16(uint32_t dst, const void* src) {
    asm volatile("cp.async.cg.shared.global [%0], [%1], 16;"
                 :: "r"(dst), "l"(src) : "memory");
}
__device__ __forceinline__ void cp_commit() {
    asm volatile("cp.async.commit_group;" ::: "memory");
}
template <int N>
__device__ __forceinline__ void cp_wait() {
    asm volatile("cp.async.wait_group %0;" :: "n"(N) : "memory");
}
__device__ __forceinline__ float f2tf_f(float x) {
    uint32_t r;
    asm("cvt.rna.tf32.f32 %0, %1;" : "=r"(r) : "f"(x));
    return __uint_as_float(r);
}
__device__ __forceinline__ uint32_t f2tf_u(uint32_t x) {
    uint32_t r;
    asm("cvt.rna.tf32.f32 %0, %1;" : "=r"(r) : "r"(x));
    return r;
}
__device__ __forceinline__ void ldsm4(uint32_t* r, uint32_t addr) {
    asm volatile("ldmatrix.sync.aligned.m8n8.x4.shared.b16 {%0,%1,%2,%3}, [%4];"
                 : "=r"(r[0]), "=r"(r[1]), "=r"(r[2]), "=r"(r[3]) : "r"(addr));
}
__device__ __forceinline__ void mma_tf32(float* c, const uint32_t* a,
                                         const uint32_t* b) {
    asm volatile(
        "mma.sync.aligned.m16n8k8.row.col.f32.tf32.tf32.f32 "
        "{%0,%1,%2,%3}, {%4,%5,%6,%7}, {%8,%9}, {%0,%1,%2,%3};"
        : "+f"(c[0]), "+f"(c[1]), "+f"(c[2]), "+f"(c[3])
        : "r"(a[0]), "r"(a[1]), "r"(a[2]), "r"(a[3]), "r"(b[0]), "r"(b[1]));
}

// ===========================================================================
// Fused weight transpose + tf32 round: WT_z[n][k] = round(W_z[k][n]), z=0..3
// ===========================================================================
__global__ void __launch_bounds__(256) transpose_kernel(
    const float* __restrict__ w0, const float* __restrict__ w1,
    const float* __restrict__ w2, const float* __restrict__ w3,
    float* __restrict__ outbase)
{
    __shared__ float t[32][33];
    const int z = blockIdx.z;
    const float* in = (z == 0) ? w0 : (z == 1) ? w1 : (z == 2) ? w2 : w3;
    float* out = outbase + (size_t)z * D_MODEL * D_MODEL;
    const int bx = blockIdx.x * 32, by = blockIdx.y * 32;
#pragma unroll
    for (int i = threadIdx.y; i < 32; i += 8)
        t[i][threadIdx.x] = f2tf_f(in[(size_t)(by + i) * D_MODEL + bx + threadIdx.x]);
    __syncthreads();
#pragma unroll
    for (int i = threadIdx.y; i < 32; i += 8)
        out[(size_t)(bx + i) * D_MODEL + by + threadIdx.x] = t[threadIdx.x][i];
}

// ===========================================================================
// TF32 mma.sync GEMM core (R16-proven). CTA 128x128, BK=32, 8 warps,
// warp 64x32, 2-stage cp.async double buffer, SSTR=36.
// ===========================================================================
#define BK      32
#define SSTR    36
#define NKIT    (D_MODEL / BK)        // 32
#define BUFF    (128 * SSTR)          // floats per buffer (4608)
#define BUFB    (BUFF * 4)            // bytes per buffer (18432)
static constexpr int GEMM_SMEM = 4 * BUFB;   // 2 stages x (A+B) = 73728 B

template <int DO_CVT>
__device__ __forceinline__ void gemm_body(
    const float* __restrict__ X, const float* __restrict__ WT,
    const float* __restrict__ bias, const int* __restrict__ pos,
    float* __restrict__ out, bool do_rope, bool do_round, float oscale,
    float* __restrict__ As, float* __restrict__ Bs,
    int row0, int col0)
{
    const int tid  = threadIdx.x;
    const int wid  = tid >> 5, lane = tid & 31;
    const int g    = lane >> 2;
    const int t    = lane & 3;
    const int warpM = (wid >> 2) * 64;
    const int warpN = (wid & 3) * 32;

    const int arow = lane & 15, acolh = (lane >> 4) * 4;
    uint32_t aAddr[4];
#pragma unroll
    for (int i = 0; i < 4; i++)
        aAddr[i] = smem_u32(&As[(warpM + i * 16 + arow) * SSTR + acolh]);
    const int brow = lane & 7, bjh = lane >> 4, bcolh = ((lane >> 3) & 1) * 4;
    uint32_t bAddr[2];
#pragma unroll
    for (int p = 0; p < 2; p++)
        bAddr[p] = smem_u32(&Bs[(warpN + (2 * p + bjh) * 8 + brow) * SSTR + bcolh]);

    float c[4][4][4];
#pragma unroll
    for (int i = 0; i < 4; i++)
#pragma unroll
        for (int j = 0; j < 4; j++)
#pragma unroll
            for (int q = 0; q < 4; q++) c[i][j][q] = 0.f;

    auto stage = [&](int buf, int it) {
        const float* aSrc = X  + (size_t)row0 * D_MODEL + it * BK;
        const float* bSrc = WT + (size_t)col0 * D_MODEL + it * BK;
#pragma unroll
        for (int rep = 0; rep < 4; rep++) {
            int idx = rep * 256 + tid;          // 0..1023
            int r = idx >> 3, c4 = (idx & 7) * 4;
            cp_async16(smem_u32(&As[buf * BUFF + r * SSTR + c4]),
                       aSrc + (size_t)r * D_MODEL + c4);
            cp_async16(smem_u32(&Bs[buf * BUFF + r * SSTR + c4]),
                       bSrc + (size_t)r * D_MODEL + c4);
        }
        cp_commit();
    };

    stage(0, 0);

#pragma unroll 1
    for (int it = 0; it < NKIT; it++) {
        const int buf = it & 1;
        if (it + 1 < NKIT) {
            stage(buf ^ 1, it + 1);
            cp_wait<1>();
        } else {
            cp_wait<0>();
        }
        __syncthreads();

        const uint32_t bo = (uint32_t)buf * BUFB;
#pragma unroll
        for (int ks = 0; ks < 4; ks++) {
            const uint32_t ko = bo + ks * 32;   // 8 floats = 32 bytes
            uint32_t af[4][4], bf[2][4];
#pragma unroll
            for (int i = 0; i < 4; i++) ldsm4(af[i], aAddr[i] + ko);
#pragma unroll
            for (int p = 0; p < 2; p++) ldsm4(bf[p], bAddr[p] + ko);
            if (DO_CVT) {
#pragma unroll
                for (int i = 0; i < 4; i++)
#pragma unroll
                    for (int q = 0; q < 4; q++) af[i][q] = f2tf_u(af[i][q]);
            }
#pragma unroll
            for (int i = 0; i < 4; i++)
#pragma unroll
                for (int j = 0; j < 4; j++)
                    mma_tf32(c[i][j], af[i], &bf[j >> 1][(j & 1) * 2]);
        }
        __syncthreads();
    }

    float invf[4];
    if (do_rope) {
#pragma unroll
        for (int j = 0; j < 4; j++) {
            int cg = col0 + warpN + j * 8 + 2 * t;
            int ii = (cg & (HEAD_DIM - 1)) >> 1;
            invf[j] = expf(-0.287823137f * (float)ii);   // ln(1e4)/32
        }
    }
#pragma unroll
    for (int i = 0; i < 4; i++) {
        const int r0 = row0 + warpM + i * 16 + g;
        const int r1 = r0 + 8;
        float p0 = 0.f, p1 = 0.f;
        if (do_rope) { p0 = (float)pos[r0]; p1 = (float)pos[r1]; }
#pragma unroll
        for (int j = 0; j < 4; j++) {
            const int cg = col0 + warpN + j * 8 + 2 * t;
            const float b0 = bias[cg], b1 = bias[cg + 1];
            float x0 = c[i][j][0] + b0, x1 = c[i][j][1] + b1;
            float y0 = c[i][j][2] + b0, y1 = c[i][j][3] + b1;
            if (do_rope) {
                float sn, cs;
                sincosf(p0 * invf[j], &sn, &cs);
                float t0 = x0 * cs - x1 * sn, t1 = x0 * sn + x1 * cs;
                x0 = t0; x1 = t1;
                sincosf(p1 * invf[j], &sn, &cs);
                t0 = y0 * cs - y1 * sn; t1 = y0 * sn + y1 * cs;
                y0 = t0; y1 = t1;
            }
            if (do_round) {
                x0 = f2tf_f(x0 * oscale); x1 = f2tf_f(x1 * oscale);
                y0 = f2tf_f(y0 * oscale); y1 = f2tf_f(y1 * oscale);
            }
            *(float2*)&out[(size_t)r0 * D_MODEL + cg] = make_float2(x0, x1);
            *(float2*)&out[(size_t)r1 * D_MODEL + cg] = make_float2(y0, y1);
        }
    }
}

// Fused Q/K/V projection: grid.z selects input/weight/bias/output.
// Outputs tf32-rounded; Q additionally scaled by 0.125 (exact).
__global__ void __launch_bounds__(256) gemm_qkv(
    const float* __restrict__ query, const float* __restrict__ key_,
    const float* __restrict__ value, const float* __restrict__ wtbase,
    const float* __restrict__ b_q, const float* __restrict__ b_k,
    const float* __restrict__ b_v, const int* __restrict__ pos,
    float* __restrict__ oQ, float* __restrict__ oK, float* __restrict__ oV)
{
    extern __shared__ float gsm[];
    const int z = blockIdx.z;
    const float* X    = (z == 0) ? query : (z == 1) ? key_ : value;
    const float* WT   = wtbase + (size_t)z * D_MODEL * D_MODEL;
    const float* bias = (z == 0) ? b_q : (z == 1) ? b_k : b_v;
    float* out        = (z == 0) ? oQ : (z == 1) ? oK : oV;
    gemm_body<1>(X, WT, bias, pos, out, z < 2, true,
                 (z == 0) ? 0.125f : 1.0f,
                 gsm, gsm + 2 * BUFF, blockIdx.y * 128, blockIdx.x * 128);
}

// Output projection: A (g_O) already tf32-rounded by attention; no out-round.
__global__ void __launch_bounds__(256) gemm_o(
    const float* __restrict__ X, const float* __restrict__ WT,
    const float* __restrict__ bias, float* __restrict__ out)
{
    extern __shared__ float gsm[];
    gemm_body<0>(X, WT, bias, nullptr, out, false, false, 1.0f,
                 gsm, gsm + 2 * BUFF, blockIdx.y * 128, blockIdx.x * 128);
}

// ===========================================================================
// Flash attention, causal — tf32 mma for S=QK^T and O=PV. (R16 math, now
// LOAD-BALANCED: each CTA handles q-tile pair (x, 31-x) = uniform 33 k-iters.)
// 128 threads (4 warps); 64x64 tiles; Q/K/V pre-rounded+scaled by producer,
// cp.async loads with double-buffered K/V.
// ===========================================================================
#define ASTR 68
#define KVF  (64 * ASTR)                 // floats per tile buffer
#define KVB  (KVF * 4)                   // bytes per tile buffer
static constexpr int ATTN_SMEM_BYTES = 6 * KVB;   // Q + 2K + 2V + P = 104448

__global__ void __launch_bounds__(128) attn_kernel()
{
    extern __shared__ float smf[];
    float* Qs = smf;                 // [64][ASTR]
    float* Ks = Qs + KVF;            // 2 buffers
    float* Vs = Ks + 2 * KVF;        // 2 buffers
    float* Ps = Vs + 2 * KVF;        // per-warp 16-row regions

    const int tid   = threadIdx.x;
    const int w     = tid >> 5, lane = tid & 31;
    const int g     = lane >> 2, t = lane & 3;
    const int h     = blockIdx.y;
    const int b     = blockIdx.z;
    const int cb    = h * HEAD_DIM;

    const uint32_t aQ = smem_u32(&Qs[(w * 16 + (lane & 15)) * ASTR + (lane >> 4) * 4]);
    const uint32_t aP = smem_u32(&Ps[(w * 16 + (lane & 15)) * ASTR + (lane >> 4) * 4]);
    uint32_t bK[4];
#pragma unroll
    for (int p = 0; p < 4; p++)
        bK[p] = smem_u32(&Ks[((2 * p + (lane >> 4)) * 8 + (lane & 7)) * ASTR +
                             ((lane >> 3) & 1) * 4]);

    const int q0 = w * 16 + g;
    const int q1 = q0 + 8;

#pragma unroll 1
    for (int ph = 0; ph < 2; ph++) {
        const int qtile = ph ? (NQT - 1 - (int)blockIdx.x) : (int)blockIdx.x;
        const int qrow0 = b * SEQ + qtile * 64;

        __syncthreads();   // previous phase fully done with smem

        auto stage_kv = [&](int buf, int kt) {
            const int krow0 = b * SEQ + kt * 64;
#pragma unroll
            for (int itr = 0; itr < 8; itr++) {
                int e = itr * 128 + tid;
                int r = e >> 4, c = (e & 15) * 4;
                cp_async16(smem_u32(&Ks[buf * KVF + r * ASTR + c]),
                           &g_K[(size_t)(krow0 + r) * D_MODEL + cb + c]);
                cp_async16(smem_u32(&Vs[buf * KVF + r * ASTR + c]),
                           &g_V[(size_t)(krow0 + r) * D_MODEL + cb + c]);
            }
        };

        // prologue: Q + first K/V tile as one group
#pragma unroll
        for (int itr = 0; itr < 8; itr++) {
            int e = itr * 128 + tid;
            int r = e >> 4, c = (e & 15) * 4;
            cp_async16(smem_u32(&Qs[r * ASTR + c]),
                       &g_Q[(size_t)(qrow0 + r) * D_MODEL + cb + c]);
        }
        stage_kv(0, 0);
        cp_commit();

        float cO[8][4];
#pragma unroll
        for (int j = 0; j < 8; j++)
#pragma unroll
            for (int q = 0; q < 4; q++) cO[j][q] = 0.f;
        float m0 = -1e30f, m1 = -1e30f, l0 = 0.f, l1 = 0.f;

#pragma unroll 1
        for (int kt = 0; kt <= qtile; kt++) {
            __syncthreads();   // done reading buf (kt+1)&1 from iter kt-1
            if (kt + 1 <= qtile) {
                stage_kv((kt + 1) & 1, kt + 1);
                cp_commit();
                cp_wait<1>();
            } else {
                cp_wait<0>();
            }
            __syncthreads();   // data for tile kt visible to all

            const uint32_t kvbo = (uint32_t)(kt & 1) * KVB;

            // ---- S = Q @ K^T  (Q pre-scaled by 1/8) ----
            float cS[8][4];
#pragma unroll
            for (int j = 0; j < 8; j++)
#pragma unroll
                for (int q = 0; q < 4; q++) cS[j][q] = 0.f;
#pragma unroll
            for (int ks = 0; ks < 8; ks++) {
                uint32_t af[4], bf[4][4];
                ldsm4(af, aQ + ks * 32);
#pragma unroll
                for (int p = 0; p < 4; p++) ldsm4(bf[p], bK[p] + kvbo + ks * 32);
#pragma unroll
                for (int j = 0; j < 8; j++)
                    mma_tf32(cS[j], af, &bf[j >> 1][(j & 1) * 2]);
            }

            if (kt == qtile) {
#pragma unroll
                for (int j = 0; j < 8; j++) {
                    int kp = j * 8 + 2 * t;
                    if (kp     > q0) cS[j][0] = -1e30f;
                    if (kp + 1 > q0) cS[j][1] = -1e30f;
                    if (kp     > q1) cS[j][2] = -1e30f;
                    if (kp + 1 > q1) cS[j][3] = -1e30f;
                }
            }

            // ---- online softmax ----
            float mt0 = -1e30f, mt1 = -1e30f;
#pragma unroll
            for (int j = 0; j < 8; j++) {
                mt0 = fmaxf(mt0, fmaxf(cS[j][0], cS[j][1]));
                mt1 = fmaxf(mt1, fmaxf(cS[j][2], cS[j][3]));
            }
            mt0 = fmaxf(mt0, __shfl_xor_sync(0xffffffffu, mt0, 1));
            mt0 = fmaxf(mt0, __shfl_xor_sync(0xffffffffu, mt0, 2));
            mt1 = fmaxf(mt1, __shfl_xor_sync(0xffffffffu, mt1, 1));
            mt1 = fmaxf(mt1, __shfl_xor_sync(0xffffffffu, mt1, 2));
            const float mn0 = fmaxf(m0, mt0), mn1 = fmaxf(m1, mt1);
            const float f0 = __expf(m0 - mn0), f1 = __expf(m1 - mn1);
            float s0 = 0.f, s1 = 0.f;
#pragma unroll
            for (int j = 0; j < 8; j++) {
                cS[j][0] = __expf(cS[j][0] - mn0); s0 += cS[j][0];
                cS[j][1] = __expf(cS[j][1] - mn0); s0 += cS[j][1];
                cS[j][2] = __expf(cS[j][2] - mn1); s1 += cS[j][2];
                cS[j][3] = __expf(cS[j][3] - mn1); s1 += cS[j][3];
            }
            s0 += __shfl_xor_sync(0xffffffffu, s0, 1);
            s0 += __shfl_xor_sync(0xffffffffu, s0, 2);
            s1 += __shfl_xor_sync(0xffffffffu, s1, 1);
            s1 += __shfl_xor_sync(0xffffffffu, s1, 2);
            l0 = l0 * f0 + s0;  l1 = l1 * f1 + s1;
            m0 = mn0;           m1 = mn1;
#pragma unroll
            for (int j = 0; j < 8; j++) {
                cO[j][0] *= f0; cO[j][1] *= f0;
                cO[j][2] *= f1; cO[j][3] *= f1;
            }

            // ---- P to per-warp smem (tf32-rounded) ----
#pragma unroll
            for (int j = 0; j < 8; j++) {
                *(float2*)&Ps[q0 * ASTR + j * 8 + 2 * t] =
                    make_float2(f2tf_f(cS[j][0]), f2tf_f(cS[j][1]));
                *(float2*)&Ps[q1 * ASTR + j * 8 + 2 * t] =
                    make_float2(f2tf_f(cS[j][2]), f2tf_f(cS[j][3]));
            }
            __syncwarp();

            // ---- O += P @ V ----
#pragma unroll
            for (int ks = 0; ks < 8; ks++) {
                uint32_t ap[4];
                ldsm4(ap, aP + ks * 32);
                const float* vb = &Vs[(kt & 1) * KVF + (ks * 8 + t) * ASTR + g];
#pragma unroll
                for (int j = 0; j < 8; j++) {
                    uint32_t bv[2];
                    bv[0] = __float_as_uint(vb[j * 8]);
                    bv[1] = __float_as_uint(vb[4 * ASTR + j * 8]);
                    mma_tf32(cO[j], ap, bv);
                }
            }
        }

        // ---- epilogue: normalize, round (feeds gemm_o), store ----
        const float inv0 = 1.f / l0, inv1 = 1.f / l1;
        float* dst0 = &g_O[(size_t)(qrow0 + q0) * D_MODEL + cb];
        float* dst1 = &g_O[(size_t)(qrow0 + q1) * D_MODEL + cb];
#pragma unroll
        for (int j = 0; j < 8; j++) {
            *(float2*)&dst0[j * 8 + 2 * t] =
                make_float2(f2tf_f(cO[j][0] * inv0), f2tf_f(cO[j][1] * inv0));
            *(float2*)&dst1[j * 8 + 2 * t] =
                make_float2(f2tf_f(cO[j][2] * inv1), f2tf_f(cO[j][3] * inv1));
        }
    }
}

// ---------------------------------------------------------------------------
extern "C" void kernel_launch(void* const* d_in, const int* in_sizes, int n_in,
                              void* d_out, int out_size)
{
    (void)in_sizes; (void)n_in; (void)out_size;
    const float* query = (const float*)d_in[0];
    const float* key_  = (const float*)d_in[1];
    const float* value = (const float*)d_in[2];
    const int*   pos   = (const int*)d_in[3];
    const float* w_q   = (const float*)d_in[4];
    const float* b_q   = (const float*)d_in[5];
    const float* w_k   = (const float*)d_in[6];
    const float* b_k   = (const float*)d_in[7];
    const float* w_v   = (const float*)d_in[8];
    const float* b_v   = (const float*)d_in[9];
    const float* w_o   = (const float*)d_in[10];
    const float* b_o   = (const float*)d_in[11];
    float* out = (float*)d_out;

    float *pQ, *pK, *pV, *pO, *pWT;
    cudaGetSymbolAddress((void**)&pQ, g_Q);
    cudaGetSymbolAddress((void**)&pK, g_K);
    cudaGetSymbolAddress((void**)&pV, g_V);
    cudaGetSymbolAddress((void**)&pO, g_O);
    cudaGetSymbolAddress((void**)&pWT, g_WT);
    float* wto = pWT + 3 * (size_t)D_MODEL * D_MODEL;

    cudaFuncSetAttribute(attn_kernel,
                         cudaFuncAttributeMaxDynamicSharedMemorySize,
                         ATTN_SMEM_BYTES);
    cudaFuncSetAttribute(gemm_qkv,
                         cudaFuncAttributeMaxDynamicSharedMemorySize, GEMM_SMEM);
    cudaFuncSetAttribute(gemm_o,
                         cudaFuncAttributeMaxDynamicSharedMemorySize, GEMM_SMEM);

    transpose_kernel<<<dim3(32, 32, 4), dim3(32, 8)>>>(w_q, w_k, w_v, w_o, pWT);

    gemm_qkv<<<dim3(D_MODEL / 128, ROWS / 128, 3), 256, GEMM_SMEM>>>(
        query, key_, value, pWT, b_q, b_k, b_v, pos, pQ, pK, pV);

    attn_kernel<<<dim3(NQT / 2, NUM_HEADS, BATCH), 128, ATTN_SMEM_BYTES>>>();

    gemm_o<<<dim3(D_MODEL / 128, ROWS / 128), 256, GEMM_SMEM>>>(pO, wto, b_o, out);
}